// round 6
// baseline (speedup 1.0000x reference)
#include <cuda_runtime.h>

// ---------------------------------------------------------------------------
// DataReUploadingLinear, Round 4:
//  * 4x8 thread tile with 4-way k-split (512 thr) -> smem crossbar traffic
//    768KB/matmul (was 1.5MB), shfl-combine across k-lanes.
//  * expm: s=6 scaling + degree-16 Paterson-Stockmeyer (A4 blocks):
//    12 matmuls (3 powers + 3 Horner + 6 squarings).
//  * Persistent CTAs + atomic job counter (no wave quantization).
// ---------------------------------------------------------------------------

#define DIM      64
#define NPAULI   4096
#define S        68                  // smem row stride: rows 16B-aligned
#define PL       (64 * S)            // plane floats (4352)
#define NTHREADS 512
#define INV_SCALE (1.0f / 64.0f)     // 1 / 2^s, s = 6
#define NSQ      6
#define GRID     152

typedef unsigned long long u64;

__device__ float2 g_Up[4][DIM * DIM];
__device__ int    g_flag;            // finished param blocks
__device__ int    g_ctr;             // persistent job counter

__device__ __forceinline__ u64 pk2(float lo, float hi) {
    u64 r; asm("mov.b64 %0, {%1, %2};" : "=l"(r) : "f"(lo), "f"(hi)); return r;
}
__device__ __forceinline__ u64 f2fma(u64 a, u64 b, u64 c) {
    u64 d; asm("fma.rn.f32x2 %0, %1, %2, %3;" : "=l"(d) : "l"(a), "l"(b), "l"(c));
    return d;
}
__device__ __forceinline__ u64 f2add(u64 a, u64 b) {
    u64 d; asm("add.rn.f32x2 %0, %1, %2;" : "=l"(d) : "l"(a), "l"(b));
    return d;
}

// Z = [G(A)] + X*Y, complex 64x64 in smem planes (stride S).
// Thread tile 4 rows x 8 cols, k split 4 ways over lanes (klane = tid&3),
// combine via shfl_xor(1,2). G = c0 I + c1 A + c2 A2 + c3 A3 (klane 0 only).
template <bool WITHG>
__device__ __forceinline__ void cmm(
    const float* __restrict__ Xr, const float* __restrict__ Xi,
    const float* __restrict__ Yr, const float* __restrict__ Yi,
    float* __restrict__ Zr, float* __restrict__ Zi,
    const float* __restrict__ Ar, const float* __restrict__ Ai,
    const float* __restrict__ A2r, const float* __restrict__ A2i,
    const float* __restrict__ A3r, const float* __restrict__ A3i,
    float c0, float c1, float c2, float c3)
{
    const int tid   = threadIdx.x;
    const int i0    = (tid >> 5) * 4;          // 16 row groups of 4
    const int tx    = (tid >> 2) & 7;          // 8 col groups of 8
    const int j0    = tx * 8;
    const int klane = tid & 3;                 // k quarter
    const int kbase = klane * 16;

    u64 crp[4][4], cim[4][4];
#pragma unroll
    for (int a = 0; a < 4; a++)
#pragma unroll
        for (int p = 0; p < 4; p++) {
            if (WITHG && klane == 0) {
                const int i = i0 + a, j = j0 + 2 * p;
                const int o0 = i * S + j, o1 = o0 + 1;
                float g0r = c1 * Ar[o0] + c2 * A2r[o0] + c3 * A3r[o0]
                          + ((i == j) ? c0 : 0.f);
                float g1r = c1 * Ar[o1] + c2 * A2r[o1] + c3 * A3r[o1]
                          + ((i == j + 1) ? c0 : 0.f);
                float g0i = c1 * Ai[o0] + c2 * A2i[o0] + c3 * A3i[o0];
                float g1i = c1 * Ai[o1] + c2 * A2i[o1] + c3 * A3i[o1];
                crp[a][p] = pk2(g0r, g1r);
                cim[a][p] = pk2(g0i, g1i);
            } else {
                crp[a][p] = 0ull; cim[a][p] = 0ull;
            }
        }

    // k rotation per klane staggers X-load banks (avoids 2-way conflict).
#pragma unroll 2
    for (int kb = 0; kb < 16; kb += 2) {
        const int kk0 = (kb + 2 * klane) & 15;
        const int kg  = kbase + kk0;

        float2 xr2[4], xi2[4];
#pragma unroll
        for (int a = 0; a < 4; a++) {
            xr2[a] = *(const float2*)&Xr[(i0 + a) * S + kg];
            xi2[a] = *(const float2*)&Xi[(i0 + a) * S + kg];
        }
#pragma unroll
        for (int kk = 0; kk < 2; kk++) {
            const int row = kg + kk;
            const ulonglong2 ra = *(const ulonglong2*)&Yr[row * S + j0];
            const ulonglong2 rb = *(const ulonglong2*)&Yr[row * S + j0 + 4];
            const ulonglong2 qa = *(const ulonglong2*)&Yi[row * S + j0];
            const ulonglong2 qb = *(const ulonglong2*)&Yi[row * S + j0 + 4];
            const u64 yr[4] = { ra.x, ra.y, rb.x, rb.y };
            const u64 yi[4] = { qa.x, qa.y, qb.x, qb.y };
#pragma unroll
            for (int a = 0; a < 4; a++) {
                const float xr = kk ? xr2[a].y : xr2[a].x;
                const float xi = kk ? xi2[a].y : xi2[a].x;
                const u64 xrr = pk2(xr, xr);
                const u64 xnn = pk2(-xi, -xi);
                const u64 xii = pk2(xi, xi);
#pragma unroll
                for (int p = 0; p < 4; p++) {
                    crp[a][p] = f2fma(xrr, yr[p], crp[a][p]);
                    crp[a][p] = f2fma(xnn, yi[p], crp[a][p]);
                    cim[a][p] = f2fma(xrr, yi[p], cim[a][p]);
                    cim[a][p] = f2fma(xii, yr[p], cim[a][p]);
                }
            }
        }
    }

    // combine across the 4 k-lanes (bits 0-1 of lane id)
#pragma unroll
    for (int a = 0; a < 4; a++)
#pragma unroll
        for (int p = 0; p < 4; p++) {
            u64 v = crp[a][p];
            v = f2add(v, __shfl_xor_sync(0xffffffffu, v, 1));
            v = f2add(v, __shfl_xor_sync(0xffffffffu, v, 2));
            crp[a][p] = v;
            u64 w = cim[a][p];
            w = f2add(w, __shfl_xor_sync(0xffffffffu, w, 1));
            w = f2add(w, __shfl_xor_sync(0xffffffffu, w, 2));
            cim[a][p] = w;
        }

    // each k-lane stores its own column pair (p = klane)
#pragma unroll
    for (int a = 0; a < 4; a++) {
        *(u64*)&Zr[(i0 + a) * S + j0 + 2 * klane] = crp[a][klane];
        *(u64*)&Zi[(i0 + a) * S + j0 + 2 * klane] = cim[a][klane];
    }
}

__global__ void reset_kernel() { g_flag = 0; g_ctr = 0; }

// Persistent kernel: job < nreps -> build Up[job]; else build Ud for sample
// (job - nreps), wait for all Up, run circuit, write out.
__global__ __launch_bounds__(NTHREADS)
void build_kernel(const float* __restrict__ x,
                  const float* __restrict__ weight,
                  const float* __restrict__ bias,
                  float* __restrict__ out,
                  int nreps, int njobs)
{
    extern __shared__ float sm[];
    float* Ar  = sm + 0 * PL;  float* Ai  = sm + 1 * PL;
    float* A2r = sm + 2 * PL;  float* A2i = sm + 3 * PL;
    float* A3r = sm + 4 * PL;  float* A3i = sm + 5 * PL;
    float* A4r = sm + 6 * PL;  float* A4i = sm + 7 * PL;
    float* Br  = sm + 8 * PL;  float* Bi  = sm + 9 * PL;
    float* Cr  = sm + 10 * PL; float* Ci  = sm + 11 * PL;
    __shared__ float2 psiA[DIM], psiB[DIM];
    __shared__ int s_job;

    const int tid = threadIdx.x;

    for (;;) {
        __syncthreads();                       // smem reuse + s_job protect
        if (tid == 0) s_job = atomicAdd(&g_ctr, 1);
        __syncthreads();
        const int job = s_job;
        if (job >= njobs) return;
        const bool is_param = (job < nreps);

        // ---- 1. Pauli coefficients into Br[0..4095] ----
        if (is_param) {
            const float* wrow = weight + (size_t)job * (NPAULI - 1);
            for (int p = tid; p < NPAULI; p += NTHREADS)
                Br[p] = (p == 0) ? 0.f : wrow[p - 1];
        } else {
            const float* xrow = x + (size_t)(job - nreps) * 4000;
            for (int p = tid; p < NPAULI; p += NTHREADS)
                Br[p] = (p < 4000) ? xrow[p] : 0.f;
        }
        __syncthreads();

        // ---- 2. D[m][t] = coef(p(m,t)) * (-i)^popc(t&m) ----
        for (int idx = tid; idx < NPAULI; idx += NTHREADS) {
            const int m = idx >> 6, t = idx & 63;
            const int mt = m ^ t;
            int p = 0;
#pragma unroll
            for (int k = 0; k < 6; k++)
                p |= (((mt >> k) & 1) << (2 * k)) | (((t >> k) & 1) << (2 * k + 1));
            const float v = Br[p];
            const int c = __popc(t & m) & 3;
            float re, im;
            switch (c) {
                case 0:  re =  v; im = 0.f; break;
                case 1:  re = 0.f; im = -v; break;
                case 2:  re = -v; im = 0.f; break;
                default: re = 0.f; im =  v; break;
            }
            Cr[idx] = re; Ci[idx] = im;
        }
        __syncthreads();

        // ---- 3. 64-pt WHT over t for each m ----
        for (int s = 0; s < 6; s++) {
            const int half = 1 << s;
            for (int n = tid; n < 2048; n += NTHREADS) {
                const int m = n >> 5, r = n & 31;
                const int t0 = ((r >> s) << (s + 1)) | (r & (half - 1));
                const int a0 = m * 64 + t0, a1 = a0 + half;
                const float ur = Cr[a0], ui = Ci[a0];
                const float vr = Cr[a1], vi = Ci[a1];
                Cr[a0] = ur + vr; Ci[a0] = ui + vi;
                Cr[a1] = ur - vr; Ci[a1] = ui - vi;
            }
            __syncthreads();
        }

        // ---- 4. A = -i*H/2^s :  H[i][i^m] = W[m][i] ----
        for (int idx = tid; idx < NPAULI; idx += NTHREADS) {
            const int m = idx >> 6, i = idx & 63;
            const int j = i ^ m;
            const float hr = Cr[m * 64 + i], hi = Ci[m * 64 + i];
            Ar[i * S + j] =  hi * INV_SCALE;
            Ai[i * S + j] = -hr * INV_SCALE;
        }
        __syncthreads();

        // ---- 5. powers A2, A3, A4 ----
        cmm<false>(Ar, Ai, Ar, Ai, A2r, A2i,
                   Ar, Ai, A2r, A2i, A3r, A3i, 0, 0, 0, 0);
        __syncthreads();
        cmm<false>(Ar, Ai, A2r, A2i, A3r, A3i,
                   Ar, Ai, A2r, A2i, A3r, A3i, 0, 0, 0, 0);
        __syncthreads();
        cmm<false>(A2r, A2i, A2r, A2i, A4r, A4i,
                   Ar, Ai, A2r, A2i, A3r, A3i, 0, 0, 0, 0);
        __syncthreads();

        // ---- 6. degree-16 PS with A4 blocks ----
        {   // B = G3' = I/12! + A/13! + A2/14! + A3/15! + A4/16!
            const float c0 = 2.08767570e-9f,  c1 = 1.60590438e-10f;
            const float c2 = 1.14707456e-11f, c3 = 7.64716373e-13f;
            const float c4 = 4.77947733e-14f;
            for (int idx = tid; idx < NPAULI; idx += NTHREADS) {
                const int i = idx >> 6, j = idx & 63;
                const int o = i * S + j;
                float gr = c1 * Ar[o] + c2 * A2r[o] + c3 * A3r[o] + c4 * A4r[o];
                float gi = c1 * Ai[o] + c2 * A2i[o] + c3 * A3i[o] + c4 * A4i[o];
                if (i == j) gr += c0;
                Br[o] = gr; Bi[o] = gi;
            }
        }
        __syncthreads();
        // C = G2 + A4*B   (I/8! + A/9! + A2/10! + A3/11!)
        cmm<true>(A4r, A4i, Br, Bi, Cr, Ci, Ar, Ai, A2r, A2i, A3r, A3i,
                  2.48015873e-5f, 2.75573192e-6f, 2.75573192e-7f, 2.50521084e-8f);
        __syncthreads();
        // B = G1 + A4*C   (I/4! + A/5! + A2/6! + A3/7!)
        cmm<true>(A4r, A4i, Cr, Ci, Br, Bi, Ar, Ai, A2r, A2i, A3r, A3i,
                  4.16666667e-2f, 8.33333333e-3f, 1.38888889e-3f, 1.98412698e-4f);
        __syncthreads();
        // C = G0 + A4*B   (I + A + A2/2 + A3/6)
        cmm<true>(A4r, A4i, Br, Bi, Cr, Ci, Ar, Ai, A2r, A2i, A3r, A3i,
                  1.f, 1.f, 0.5f, 1.f / 6.f);
        __syncthreads();

        // ---- 7. 6 squarings, ping-pong C <-> B (ends in C) ----
        float *qr = Cr, *qi = Ci, *pr = Br, *pi = Bi;
#pragma unroll 1
        for (int q = 0; q < NSQ; q++) {
            cmm<false>(qr, qi, qr, qi, pr, pi,
                       Ar, Ai, A2r, A2i, A3r, A3i, 0, 0, 0, 0);
            __syncthreads();
            float* t;
            t = qr; qr = pr; pr = t;
            t = qi; qi = pi; pi = t;
        }

        // ---- 8a. parameter job: publish Up and signal ----
        if (is_param) {
            for (int idx = tid; idx < DIM * DIM; idx += NTHREADS) {
                const int i = idx >> 6, j = idx & 63;
                g_Up[job][idx] = make_float2(qr[i * S + j], qi[i * S + j]);
            }
            __threadfence();
            __syncthreads();
            if (tid == 0) atomicAdd(&g_flag, 1);
            continue;
        }

        // ---- 8b. data job: wait for Up, run circuit ----
        if (tid == 0) {
            int v;
            do {
                asm volatile("ld.global.acquire.gpu.b32 %0, [%1];"
                             : "=r"(v) : "l"(&g_flag));
                if (v < nreps) __nanosleep(64);
            } while (v < nreps);
        }
        __threadfence();
        if (tid < DIM) psiA[tid] = make_float2(tid == 0 ? 1.f : 0.f, 0.f);
        __syncthreads();

        if (tid < 256) {
            float2* pin = psiA;
            float2* pout = psiB;
            const int row = tid >> 2, part = tid & 3;
            const int k0 = part * 16;

            for (int r = 0; r < nreps; r++) {
                {   // pout = Ud * pin  (Ud in smem planes qr/qi)
                    float sr = 0.f, si = 0.f;
#pragma unroll
                    for (int k = k0; k < k0 + 16; k++) {
                        const float mr = qr[row * S + k], mi = qi[row * S + k];
                        const float2 v = pin[k];
                        sr = fmaf(mr, v.x, sr); sr = fmaf(-mi, v.y, sr);
                        si = fmaf(mr, v.y, si); si = fmaf(mi, v.x, si);
                    }
                    sr += __shfl_xor_sync(0xffffffffu, sr, 1);
                    sr += __shfl_xor_sync(0xffffffffu, sr, 2);
                    si += __shfl_xor_sync(0xffffffffu, si, 1);
                    si += __shfl_xor_sync(0xffffffffu, si, 2);
                    if (part == 0) pout[row] = make_float2(sr, si);
                }
                __syncwarp();
                asm volatile("bar.sync 1, 256;" ::: "memory");
                { float2* t = pin; pin = pout; pout = t; }

                {   // pout = Up[r] * pin
                    const float2* U = g_Up[r];
                    float sr = 0.f, si = 0.f;
#pragma unroll
                    for (int k = k0; k < k0 + 16; k++) {
                        const float2 u = U[row * DIM + k];
                        const float2 v = pin[k];
                        sr = fmaf(u.x, v.x, sr); sr = fmaf(-u.y, v.y, sr);
                        si = fmaf(u.x, v.y, si); si = fmaf(u.y, v.x, si);
                    }
                    sr += __shfl_xor_sync(0xffffffffu, sr, 1);
                    sr += __shfl_xor_sync(0xffffffffu, sr, 2);
                    si += __shfl_xor_sync(0xffffffffu, si, 1);
                    si += __shfl_xor_sync(0xffffffffu, si, 2);
                    if (part == 0) pout[row] = make_float2(sr, si);
                }
                __syncwarp();
                asm volatile("bar.sync 1, 256;" ::: "memory");
                { float2* t = pin; pin = pout; pout = t; }
            }

            if (tid < DIM) {
                const float2 v = pin[tid];
                out[(size_t)(job - nreps) * DIM + tid] =
                    fmaf(v.x, v.x, v.y * v.y) + bias[tid];
            }
        }
    }
}

extern "C" void kernel_launch(void* const* d_in, const int* in_sizes, int n_in,
                              void* d_out, int out_size)
{
    const float* x      = (const float*)d_in[0];   // [512, 4000]
    const float* weight = (const float*)d_in[1];   // [4, 4095]
    const float* bias   = (const float*)d_in[2];   // [64]
    float* out = (float*)d_out;                    // [512, 64]

    const int B     = in_sizes[0] / 4000;
    const int nreps = in_sizes[1] / (NPAULI - 1);
    const int njobs = nreps + B;

    const size_t smem = (size_t)12 * PL * sizeof(float);   // 208,896 B
    cudaFuncSetAttribute(build_kernel,
                         cudaFuncAttributeMaxDynamicSharedMemorySize, (int)smem);

    reset_kernel<<<1, 1>>>();
    const int grid = (njobs < GRID) ? njobs : GRID;
    build_kernel<<<grid, NTHREADS, smem>>>(x, weight, bias, out, nreps, njobs);
}

// round 8
// speedup vs baseline: 2.0243x; 2.0243x over previous
#include <cuda_runtime.h>

// ---------------------------------------------------------------------------
// DataReUploadingLinear, Round 6:
//  * cmm tile 4 rows x 2 cols, row-group == warp: X loads fully warp-uniform
//    (1 wavefront), Y loads 32x8B contiguous (2 wavefronts) -> crossbar
//    ~4.6K cyc/cmm, below the 8.2K FFMA2 floor. No k-split, no spills.
//  * expm: s=6 + degree-16 Paterson-Stockmeyer (12 matmuls) [verified R5].
//  * Persistent CTAs + job counter (no tail wave) [verified R5].
// ---------------------------------------------------------------------------

#define DIM      64
#define NPAULI   4096
#define S        68                  // smem row stride (rows 16B-aligned)
#define PL       (64 * S)            // plane floats (4352)
#define NTHREADS 512
#define INV_SCALE (1.0f / 64.0f)     // 1 / 2^s, s = 6
#define NSQ      6
#define GRID     152

typedef unsigned long long u64;

__device__ float2 g_Up[4][DIM * DIM];
__device__ int    g_flag;            // finished param jobs
__device__ int    g_ctr;             // persistent job counter

__device__ __forceinline__ u64 pk2(float lo, float hi) {
    u64 r; asm("mov.b64 %0, {%1, %2};" : "=l"(r) : "f"(lo), "f"(hi)); return r;
}
__device__ __forceinline__ u64 f2fma(u64 a, u64 b, u64 c) {
    u64 d; asm("fma.rn.f32x2 %0, %1, %2, %3;" : "=l"(d) : "l"(a), "l"(b), "l"(c));
    return d;
}
__device__ __forceinline__ u64 f2sub(u64 a, u64 b) {
    float al, ah, bl, bh;
    asm("mov.b64 {%0, %1}, %2;" : "=f"(al), "=f"(ah) : "l"(a));
    asm("mov.b64 {%0, %1}, %2;" : "=f"(bl), "=f"(bh) : "l"(b));
    return pk2(al - bl, ah - bh);
}

// Z = [G(A)] + X*Y, complex 64x64 in smem planes (stride S).
// 512 threads. Tile: 4 rows (warp-uniform: wid = tid>>5 -> rows 4*wid..+3)
// x 2 cols (lane -> j0 = 2*lane). G = c0 I + c1 A + c2 A2 + c3 A3.
template <bool WITHG>
__device__ __forceinline__ void cmm(
    const float* __restrict__ Xr, const float* __restrict__ Xi,
    const float* __restrict__ Yr, const float* __restrict__ Yi,
    float* __restrict__ Zr, float* __restrict__ Zi,
    const float* __restrict__ Ar, const float* __restrict__ Ai,
    const float* __restrict__ A2r, const float* __restrict__ A2i,
    const float* __restrict__ A3r, const float* __restrict__ A3i,
    float c0, float c1, float c2, float c3)
{
    const int tid = threadIdx.x;
    const int i0 = (tid >> 5) * 4;        // warp-uniform row group
    const int j0 = (tid & 31) * 2;        // per-lane column pair

    u64 crp[4], crn[4], cim[4];
#pragma unroll
    for (int a = 0; a < 4; a++) {
        if (WITHG) {
            const int i = i0 + a;
            const int o0 = i * S + j0, o1 = o0 + 1;
            float g0r = c1 * Ar[o0] + c2 * A2r[o0] + c3 * A3r[o0]
                      + ((i == j0)     ? c0 : 0.f);
            float g1r = c1 * Ar[o1] + c2 * A2r[o1] + c3 * A3r[o1]
                      + ((i == j0 + 1) ? c0 : 0.f);
            float g0i = c1 * Ai[o0] + c2 * A2i[o0] + c3 * A3i[o0];
            float g1i = c1 * Ai[o1] + c2 * A2i[o1] + c3 * A3i[o1];
            crp[a] = pk2(g0r, g1r);
            cim[a] = pk2(g0i, g1i);
        } else {
            crp[a] = 0ull; cim[a] = 0ull;
        }
        crn[a] = 0ull;
    }

#pragma unroll 2
    for (int k4 = 0; k4 < 64; k4 += 4) {
        // X: warp-uniform LDS.128 over 4 k's (1 wavefront each)
        float4 xr4[4], xi4[4];
#pragma unroll
        for (int a = 0; a < 4; a++) {
            xr4[a] = *(const float4*)&Xr[(i0 + a) * S + k4];
            xi4[a] = *(const float4*)&Xi[(i0 + a) * S + k4];
        }
#pragma unroll
        for (int kk = 0; kk < 4; kk++) {
            const int k = k4 + kk;
            // Y: per-lane 8B pair, 32 lanes contiguous 256B (2 wavefronts)
            const u64 yr = *(const u64*)&Yr[k * S + j0];
            const u64 yi = *(const u64*)&Yi[k * S + j0];
#pragma unroll
            for (int a = 0; a < 4; a++) {
                const float xr = (kk == 0) ? xr4[a].x : (kk == 1) ? xr4[a].y
                               : (kk == 2) ? xr4[a].z : xr4[a].w;
                const float xi = (kk == 0) ? xi4[a].x : (kk == 1) ? xi4[a].y
                               : (kk == 2) ? xi4[a].z : xi4[a].w;
                const u64 xrr = pk2(xr, xr);
                const u64 xii = pk2(xi, xi);
                crp[a] = f2fma(xrr, yr, crp[a]);
                crn[a] = f2fma(xii, yi, crn[a]);
                cim[a] = f2fma(xrr, yi, cim[a]);
                cim[a] = f2fma(xii, yr, cim[a]);
            }
        }
    }

#pragma unroll
    for (int a = 0; a < 4; a++) {
        *(u64*)&Zr[(i0 + a) * S + j0] = f2sub(crp[a], crn[a]);
        *(u64*)&Zi[(i0 + a) * S + j0] = cim[a];
    }
}

__global__ void reset_kernel() { g_flag = 0; g_ctr = 0; }

// Persistent: job < nreps -> build Up[job]; else build Ud for sample
// (job - nreps), wait for all Up, run circuit, write out.
__global__ __launch_bounds__(NTHREADS, 1)
void build_kernel(const float* __restrict__ x,
                  const float* __restrict__ weight,
                  const float* __restrict__ bias,
                  float* __restrict__ out,
                  int nreps, int njobs)
{
    extern __shared__ float sm[];
    float* Ar  = sm + 0 * PL;  float* Ai  = sm + 1 * PL;
    float* A2r = sm + 2 * PL;  float* A2i = sm + 3 * PL;
    float* A3r = sm + 4 * PL;  float* A3i = sm + 5 * PL;
    float* A4r = sm + 6 * PL;  float* A4i = sm + 7 * PL;
    float* Br  = sm + 8 * PL;  float* Bi  = sm + 9 * PL;
    float* Cr  = sm + 10 * PL; float* Ci  = sm + 11 * PL;
    __shared__ float2 psiA[DIM], psiB[DIM];
    __shared__ int s_job;

    const int tid = threadIdx.x;

    for (;;) {
        __syncthreads();                    // smem reuse + s_job protect
        if (tid == 0) s_job = atomicAdd(&g_ctr, 1);
        __syncthreads();
        const int job = s_job;
        if (job >= njobs) return;
        const bool is_param = (job < nreps);

        // ---- 1. Pauli coefficients into Br[0..4095] ----
        if (is_param) {
            const float* wrow = weight + (size_t)job * (NPAULI - 1);
            for (int p = tid; p < NPAULI; p += NTHREADS)
                Br[p] = (p == 0) ? 0.f : wrow[p - 1];
        } else {
            const float* xrow = x + (size_t)(job - nreps) * 4000;
            for (int p = tid; p < NPAULI; p += NTHREADS)
                Br[p] = (p < 4000) ? xrow[p] : 0.f;
        }
        __syncthreads();

        // ---- 2. D[m][t] = coef(p(m,t)) * (-i)^popc(t&m) ----
        for (int idx = tid; idx < NPAULI; idx += NTHREADS) {
            const int m = idx >> 6, t = idx & 63;
            const int mt = m ^ t;
            int p = 0;
#pragma unroll
            for (int k = 0; k < 6; k++)
                p |= (((mt >> k) & 1) << (2 * k)) | (((t >> k) & 1) << (2 * k + 1));
            const float v = Br[p];
            const int c = __popc(t & m) & 3;
            float re, im;
            switch (c) {
                case 0:  re =  v; im = 0.f; break;
                case 1:  re = 0.f; im = -v; break;
                case 2:  re = -v; im = 0.f; break;
                default: re = 0.f; im =  v; break;
            }
            Cr[idx] = re; Ci[idx] = im;
        }
        __syncthreads();

        // ---- 3. 64-pt WHT over t for each m ----
        for (int s = 0; s < 6; s++) {
            const int half = 1 << s;
            for (int n = tid; n < 2048; n += NTHREADS) {
                const int m = n >> 5, r = n & 31;
                const int t0 = ((r >> s) << (s + 1)) | (r & (half - 1));
                const int a0 = m * 64 + t0, a1 = a0 + half;
                const float ur = Cr[a0], ui = Ci[a0];
                const float vr = Cr[a1], vi = Ci[a1];
                Cr[a0] = ur + vr; Ci[a0] = ui + vi;
                Cr[a1] = ur - vr; Ci[a1] = ui - vi;
            }
            __syncthreads();
        }

        // ---- 4. A = -i*H/2^s :  H[i][i^m] = W[m][i] ----
        for (int idx = tid; idx < NPAULI; idx += NTHREADS) {
            const int m = idx >> 6, i = idx & 63;
            const int j = i ^ m;
            const float hr = Cr[m * 64 + i], hi = Ci[m * 64 + i];
            Ar[i * S + j] =  hi * INV_SCALE;
            Ai[i * S + j] = -hr * INV_SCALE;
        }
        __syncthreads();

        // ---- 5. powers A2, A3, A4 ----
        cmm<false>(Ar, Ai, Ar, Ai, A2r, A2i,
                   Ar, Ai, A2r, A2i, A3r, A3i, 0, 0, 0, 0);
        __syncthreads();
        cmm<false>(Ar, Ai, A2r, A2i, A3r, A3i,
                   Ar, Ai, A2r, A2i, A3r, A3i, 0, 0, 0, 0);
        __syncthreads();
        cmm<false>(A2r, A2i, A2r, A2i, A4r, A4i,
                   Ar, Ai, A2r, A2i, A3r, A3i, 0, 0, 0, 0);
        __syncthreads();

        // ---- 6. degree-16 PS with A4 blocks ----
        {   // B = G3 = I/12! + A/13! + A2/14! + A3/15! + A4/16!
            const float c0 = 2.08767570e-9f,  c1 = 1.60590438e-10f;
            const float c2 = 1.14707456e-11f, c3 = 7.64716373e-13f;
            const float c4 = 4.77947733e-14f;
            for (int idx = tid; idx < NPAULI; idx += NTHREADS) {
                const int i = idx >> 6, j = idx & 63;
                const int o = i * S + j;
                float gr = c1 * Ar[o] + c2 * A2r[o] + c3 * A3r[o] + c4 * A4r[o];
                float gi = c1 * Ai[o] + c2 * A2i[o] + c3 * A3i[o] + c4 * A4i[o];
                if (i == j) gr += c0;
                Br[o] = gr; Bi[o] = gi;
            }
        }
        __syncthreads();
        // C = G2 + A4*B   (I/8! + A/9! + A2/10! + A3/11!)
        cmm<true>(A4r, A4i, Br, Bi, Cr, Ci, Ar, Ai, A2r, A2i, A3r, A3i,
                  2.48015873e-5f, 2.75573192e-6f, 2.75573192e-7f, 2.50521084e-8f);
        __syncthreads();
        // B = G1 + A4*C   (I/4! + A/5! + A2/6! + A3/7!)
        cmm<true>(A4r, A4i, Cr, Ci, Br, Bi, Ar, Ai, A2r, A2i, A3r, A3i,
                  4.16666667e-2f, 8.33333333e-3f, 1.38888889e-3f, 1.98412698e-4f);
        __syncthreads();
        // C = G0 + A4*B   (I + A + A2/2 + A3/6)
        cmm<true>(A4r, A4i, Br, Bi, Cr, Ci, Ar, Ai, A2r, A2i, A3r, A3i,
                  1.f, 1.f, 0.5f, 1.f / 6.f);
        __syncthreads();

        // ---- 7. 6 squarings, ping-pong C <-> B (ends in C) ----
        float *qr = Cr, *qi = Ci, *pr = Br, *pi = Bi;
#pragma unroll 1
        for (int q = 0; q < NSQ; q++) {
            cmm<false>(qr, qi, qr, qi, pr, pi,
                       Ar, Ai, A2r, A2i, A3r, A3i, 0, 0, 0, 0);
            __syncthreads();
            float* t;
            t = qr; qr = pr; pr = t;
            t = qi; qi = pi; pi = t;
        }

        // ---- 8a. parameter job: publish Up and signal ----
        if (is_param) {
            for (int idx = tid; idx < DIM * DIM; idx += NTHREADS) {
                const int i = idx >> 6, j = idx & 63;
                g_Up[job][idx] = make_float2(qr[i * S + j], qi[i * S + j]);
            }
            __threadfence();
            __syncthreads();
            if (tid == 0) atomicAdd(&g_flag, 1);
            continue;
        }

        // ---- 8b. data job: wait for Up, run circuit ----
        if (tid == 0) {
            int v;
            do {
                asm volatile("ld.global.acquire.gpu.b32 %0, [%1];"
                             : "=r"(v) : "l"(&g_flag));
                if (v < nreps) __nanosleep(64);
            } while (v < nreps);
        }
        __threadfence();
        if (tid < DIM) psiA[tid] = make_float2(tid == 0 ? 1.f : 0.f, 0.f);
        __syncthreads();

        if (tid < 256) {
            float2* pin = psiA;
            float2* pout = psiB;
            const int row = tid >> 2, part = tid & 3;
            const int k0 = part * 16;

            for (int r = 0; r < nreps; r++) {
                {   // pout = Ud * pin  (Ud in smem planes qr/qi)
                    float sr = 0.f, si = 0.f;
#pragma unroll
                    for (int k = k0; k < k0 + 16; k++) {
                        const float mr = qr[row * S + k], mi = qi[row * S + k];
                        const float2 v = pin[k];
                        sr = fmaf(mr, v.x, sr); sr = fmaf(-mi, v.y, sr);
                        si = fmaf(mr, v.y, si); si = fmaf(mi, v.x, si);
                    }
                    sr += __shfl_xor_sync(0xffffffffu, sr, 1);
                    sr += __shfl_xor_sync(0xffffffffu, sr, 2);
                    si += __shfl_xor_sync(0xffffffffu, si, 1);
                    si += __shfl_xor_sync(0xffffffffu, si, 2);
                    if (part == 0) pout[row] = make_float2(sr, si);
                }
                __syncwarp();
                asm volatile("bar.sync 1, 256;" ::: "memory");
                { float2* t = pin; pin = pout; pout = t; }

                {   // pout = Up[r] * pin
                    const float2* U = g_Up[r];
                    float sr = 0.f, si = 0.f;
#pragma unroll
                    for (int k = k0; k < k0 + 16; k++) {
                        const float2 u = U[row * DIM + k];
                        const float2 v = pin[k];
                        sr = fmaf(u.x, v.x, sr); sr = fmaf(-u.y, v.y, sr);
                        si = fmaf(u.x, v.y, si); si = fmaf(u.y, v.x, si);
                    }
                    sr += __shfl_xor_sync(0xffffffffu, sr, 1);
                    sr += __shfl_xor_sync(0xffffffffu, sr, 2);
                    si += __shfl_xor_sync(0xffffffffu, si, 1);
                    si += __shfl_xor_sync(0xffffffffu, si, 2);
                    if (part == 0) pout[row] = make_float2(sr, si);
                }
                __syncwarp();
                asm volatile("bar.sync 1, 256;" ::: "memory");
                { float2* t = pin; pin = pout; pout = t; }
            }

            if (tid < DIM) {
                const float2 v = pin[tid];
                out[(size_t)(job - nreps) * DIM + tid] =
                    fmaf(v.x, v.x, v.y * v.y) + bias[tid];
            }
        }
    }
}

extern "C" void kernel_launch(void* const* d_in, const int* in_sizes, int n_in,
                              void* d_out, int out_size)
{
    const float* x      = (const float*)d_in[0];   // [512, 4000]
    const float* weight = (const float*)d_in[1];   // [4, 4095]
    const float* bias   = (const float*)d_in[2];   // [64]
    float* out = (float*)d_out;                    // [512, 64]

    const int B     = in_sizes[0] / 4000;
    const int nreps = in_sizes[1] / (NPAULI - 1);
    const int njobs = nreps + B;

    const size_t smem = (size_t)12 * PL * sizeof(float);   // 208,896 B
    cudaFuncSetAttribute(build_kernel,
                         cudaFuncAttributeMaxDynamicSharedMemorySize, (int)smem);

    reset_kernel<<<1, 1>>>();
    const int grid = (njobs < GRID) ? njobs : GRID;
    build_kernel<<<grid, NTHREADS, smem>>>(x, weight, bias, out, nreps, njobs);
}